// round 15
// baseline (speedup 1.0000x reference)
#include <cuda_runtime.h>
#include <cuda_bf16.h>
#include <cstdint>

// ---------------- problem constants ----------------
#define BB   8
#define NN   2048
#define DIN  2
#define DS   32
#define DO   32
#define GE   8
#define HID  32
#define DCAT 66
#define DGI  74
#define DBASIS 396
#define GOUT 96

#define TOTN (BB*NN)
#define SZ66 ((size_t)TOTN*DCAT)
#define SZ32 ((size_t)TOTN*DO)

#define NJ 9                 // n8 blocks (72 cols, 66 used)
#define NKS 128              // k16 blocks
#define NMB 128              // m16 blocks per (z,b) image
#define PACK_ELEMS ((size_t)BB*NJ*NKS*32)        // uint4 per B pack image
#define APACK_ELEMS ((size_t)16*NMB*NKS*32)      // uint4 per A plane (134MB)

__device__ float g_scratch[6*1081344 + 2*524288];
__device__ uint4 g_packA[PACK_ELEMS];       // packed X or C (B-operand, SHARED by both supports)
__device__ uint4 g_packB[2*PACK_ELEMS];     // packed T0 (slot0) / T2 (slot1)
__device__ uint4 g_packAh[APACK_ELEMS];     // A fragments, high bf16 plane
__device__ uint4 g_packAl[APACK_ELEMS];     // A fragments, low-residual plane

#define OFF_X  ((size_t)0)
#define OFF_C  (SZ66)
#define OFF_T0 (2*SZ66)
#define OFF_T1 (3*SZ66)
#define OFF_T2 (4*SZ66)
#define OFF_T3 (5*SZ66)
#define OFF_ST (6*SZ66)
#define OFF_R  (6*SZ66 + SZ32)

__device__ __forceinline__ float sigmoidf_(float x) {
    return 1.0f / (1.0f + __expf(-x));
}

__device__ __forceinline__ void mma_bf16(float c[4], const uint32_t a[4], const uint32_t b[2]) {
    asm volatile(
        "mma.sync.aligned.m16n8k16.row.col.f32.bf16.bf16.f32 "
        "{%0,%1,%2,%3},{%4,%5,%6,%7},{%8,%9},{%0,%1,%2,%3};"
        : "+f"(c[0]), "+f"(c[1]), "+f"(c[2]), "+f"(c[3])
        : "r"(a[0]), "r"(a[1]), "r"(a[2]), "r"(a[3]), "r"(b[0]), "r"(b[1]));
}

__device__ __forceinline__ void cp_async16(void* smem, const void* gmem) {
    uint32_t s = (uint32_t)__cvta_generic_to_shared(smem);
    asm volatile("cp.async.cg.shared.global [%0], [%1], 16;\n" :: "r"(s), "l"(gmem));
}
__device__ __forceinline__ void cp_commit() {
    asm volatile("cp.async.commit_group;\n" ::: "memory");
}
template<int N>
__device__ __forceinline__ void cp_wait() {
    asm volatile("cp.async.wait_group %0;\n" :: "n"(N) : "memory");
}

// split float2 -> bf16x2 high + bf16x2 low-residual
__device__ __forceinline__ void split2(float2 v, uint32_t& h, uint32_t& l) {
    __nv_bfloat162 hh = __float22bfloat162_rn(v);
    h = *(uint32_t*)&hh;
    float2 r;
    r.x = v.x - __low2float(hh);
    r.y = v.y - __high2float(hh);
    __nv_bfloat162 ll = __float22bfloat162_rn(r);
    l = *(uint32_t*)&ll;
}

// pack one 16-node x 66-col tile (smem) -> B fragment-native h/l image.
template<int TS>
__device__ __forceinline__ void pack_tile(const float (*tile)[TS], uint4* dst,
                                          int b, int kb, int t)
{
    const int j    = t >> 5;
    const int lane = t & 31;
    const int g    = lane >> 2;
    const int tg   = lane & 3;
    const int n    = j*8 + g;

    float v0 = 0.f, v1 = 0.f, v2 = 0.f, v3 = 0.f;
    if (n < DCAT) {
        v0 = tile[2*tg    ][n];
        v1 = tile[2*tg + 1][n];
        v2 = tile[2*tg + 8][n];
        v3 = tile[2*tg + 9][n];
    }
    uint32_t h01, l01, h89, l89;
    split2(make_float2(v0, v1), h01, l01);
    split2(make_float2(v2, v3), h89, l89);

    uint4 o; o.x = h01; o.y = h89; o.z = l01; o.w = l89;
    dst[((size_t)(b*NJ + j)*NKS + kb)*32 + lane] = o;
}

// ---------------------------------------------------------------------------
// Kernel 1: prep — gate MLP -> mr -> state; write X and packed X
// ---------------------------------------------------------------------------
__global__ __launch_bounds__(512) void prep_kernel(
                            const float* __restrict__ xt,
                            const float* __restrict__ s1,
                            const float* __restrict__ s2,
                            const float* __restrict__ ge,
                            const float* __restrict__ mlp_w,
                            const float* __restrict__ mlp_b,
                            float* __restrict__ gX,
                            float* __restrict__ gstate,
                            uint4* __restrict__ packX)
{
    __shared__ float sg[16][DGI];
    const int t  = threadIdx.x;
    const int nb = blockIdx.x * 16;

    for (int idx = t; idx < 16 * DGI; idx += 512) {
        int nn = idx / DGI, i = idx % DGI;
        int node = nb + nn;
        float v;
        if (i < DIN)            v = xt[node*DIN + i];
        else if (i < DIN+DS)    v = s1[node*DS + (i-DIN)];
        else if (i < DIN+2*DS)  v = s2[node*DS + (i-DIN-DS)];
        else                    v = ge[node*GE + (i-DIN-2*DS)];
        sg[nn][i] = v;
    }
    __syncthreads();

    for (int idx = t; idx < 16 * DCAT; idx += 512) {
        int nn = idx / DCAT, i = idx % DCAT;
        gX[(size_t)(nb+nn)*DCAT + i] = sg[nn][i];
    }

    const int n = t >> 5;
    const int c = t & 31;
    float acc = mlp_b[c];
#pragma unroll 8
    for (int i = 0; i < DGI; i++)
        acc = fmaf(sg[n][i], mlp_w[i*DO + c], acc);
    float mr = sigmoidf_(acc);

    int node = nb + n;
    float a = s1[node*DS + c];
    float b = s2[node*DS + c];
    gstate[node*DS + c] = mr*a + (1.0f - mr)*b;

    if (t < 288) {
        const int bb = nb >> 11;
        const int kb = (nb & 2047) >> 4;
        pack_tile<DGI>(sg, packX, bb, kb, t);
    }
}

// ---------------------------------------------------------------------------
// Pack kernel (T0/T2): grid (128, 8, 2)
// ---------------------------------------------------------------------------
__global__ __launch_bounds__(288) void pack_kernel(const float* __restrict__ src,
                                                   size_t srcStride,
                                                   uint4* __restrict__ dst)
{
    __shared__ float tile[16][68];
    const int t  = threadIdx.x;
    const int kb = blockIdx.x;
    const int b  = blockIdx.y;
    const int z  = blockIdx.z;
    src += (size_t)z * srcStride;
    dst += (size_t)z * PACK_ELEMS;
    const int node0 = b*NN + kb*16;

    for (int idx = t; idx < 16*DCAT; idx += 288) {
        int r = idx / DCAT, c = idx - r*DCAT;
        tile[r][c] = src[(size_t)(node0 + r)*DCAT + c];
    }
    __syncthreads();
    pack_tile<68>(tile, dst, b, kb, t);
}

// ---------------------------------------------------------------------------
// Kernel 2a: FIRST GEMM — A from fp32 (scattered LDG), in-reg split,
// writes packed A fragment planes for later launches.
// B via cp.async 4-stage smem ring. CTA 128 thr = 4 warps x m16. grid (32,8,2)
// ---------------------------------------------------------------------------
#define STAGES 4

__global__ __launch_bounds__(128) void gemm_first(const float* __restrict__ A,
                                                  const uint4* __restrict__ Bp,
                                                  float* __restrict__ Out,
                                                  uint4* __restrict__ pAh,
                                                  uint4* __restrict__ pAl)
{
    __shared__ uint4 sB[STAGES][NJ*32];

    const int z = blockIdx.z;
    A   += (size_t)z * BB * NN * NN;
    Out += (size_t)z * 2 * SZ66;

    const int t    = threadIdx.x;
    const int w    = t >> 5;
    const int lane = t & 31;
    const int g    = lane >> 2;
    const int tg   = lane & 3;
    const int b    = blockIdx.y;
    const int zb   = z * BB + b;
    const int mb   = blockIdx.x * 4 + w;
    const int row0 = mb * 16;

    const float* Ab = A + ((size_t)b * NN + row0) * NN;
    const uint4* Bb = Bp + (size_t)b * NJ * NKS * 32;

    float acc[NJ][4];
#pragma unroll
    for (int j = 0; j < NJ; j++)
#pragma unroll
        for (int q = 0; q < 4; q++) acc[j][q] = 0.0f;

    float2 ar[2][4];

    auto ISSUE_B = [&](int ks) {
        const int slot = ks & (STAGES-1);
        cp_async16(&sB[slot][t],       Bb + ((size_t)(t >> 5)*NKS + ks)*32 + (t & 31));
        {
            int idx = t + 128;
            cp_async16(&sB[slot][idx], Bb + ((size_t)(idx >> 5)*NKS + ks)*32 + (idx & 31));
        }
        if (t < 32) {
            int idx = t + 256;
            cp_async16(&sB[slot][idx], Bb + ((size_t)(idx >> 5)*NKS + ks)*32 + (idx & 31));
        }
    };
    auto LD_A = [&](int ks, int p) {
        const int k = ks*16 + 2*tg;
        const float* ap = Ab + (size_t)g*NN + k;
        ar[p][0] = *(const float2*)(ap);
        ar[p][1] = *(const float2*)(ap + 8*NN);
        ar[p][2] = *(const float2*)(ap + 8);
        ar[p][3] = *(const float2*)(ap + 8*NN + 8);
    };

    ISSUE_B(0); cp_commit();
    ISSUE_B(1); cp_commit();
    LD_A(0, 0);

    const size_t fbase = (((size_t)zb * NMB + mb) * NKS) * 32 + lane;

    for (int ks = 0; ks < NKS; ks++) {
        const int p = ks & 1;
        if (ks + 2 < NKS) ISSUE_B(ks + 2);
        cp_commit();
        if (ks + 1 < NKS) LD_A(ks + 1, p ^ 1);

        cp_wait<2>();
        __syncthreads();

        uint32_t ah[4], al[4];
#pragma unroll
        for (int q = 0; q < 4; q++)
            split2(ar[p][q], ah[q], al[q]);

        // persist A fragments for later launches (coalesced STG.128)
        const size_t fidx = fbase + (size_t)ks * 32;
        pAh[fidx] = make_uint4(ah[0], ah[1], ah[2], ah[3]);
        pAl[fidx] = make_uint4(al[0], al[1], al[2], al[3]);

        const uint4* bs = &sB[ks & (STAGES-1)][lane];
#pragma unroll
        for (int j = 0; j < NJ; j++) {
            uint4 bj = bs[j*32];
            uint32_t bh[2], bl[2];
            bh[0] = bj.x; bh[1] = bj.y;
            bl[0] = bj.z; bl[1] = bj.w;
            mma_bf16(acc[j], ah, bh);
            mma_bf16(acc[j], al, bh);
            mma_bf16(acc[j], ah, bl);
        }
    }

#pragma unroll
    for (int j = 0; j < NJ; j++) {
        int col = j*8 + 2*tg;
        if (col < DCAT) {
#pragma unroll
            for (int h2 = 0; h2 < 2; h2++) {
                int row = row0 + g + h2*8;
                size_t o = ((size_t)b * NN + row) * DCAT + col;
                float2 v;
                v.x = acc[j][h2*2 + 0];
                v.y = acc[j][h2*2 + 1];
                *(float2*)(Out + o) = v;
            }
        }
    }
}

// ---------------------------------------------------------------------------
// Kernel 2b: PACKED GEMM — A from fragment-native bf16 planes (coalesced),
// B via cp.async ring. Same grid/shape.
// bpStride = 0 when B image is shared by both supports (X/C), PACK_ELEMS
// when per-support (T0/T2 slots).
// ---------------------------------------------------------------------------
__global__ __launch_bounds__(128) void gemm_packed(const uint4* __restrict__ pAh,
                                                   const uint4* __restrict__ pAl,
                                                   const uint4* __restrict__ Bp,
                                                   size_t bpStride,
                                                   const float* __restrict__ Base,
                                                   float* __restrict__ Out,
                                                   float alpha, float beta)
{
    __shared__ uint4 sB[STAGES][NJ*32];

    const int z = blockIdx.z;
    Bp  += (size_t)z * bpStride;
    Out += (size_t)z * 2 * SZ66;

    const int t    = threadIdx.x;
    const int w    = t >> 5;
    const int lane = t & 31;
    const int g    = lane >> 2;
    const int tg   = lane & 3;
    const int b    = blockIdx.y;
    const int zb   = z * BB + b;
    const int mb   = blockIdx.x * 4 + w;
    const int row0 = mb * 16;

    const uint4* Bb = Bp + (size_t)b * NJ * NKS * 32;
    const size_t fbase = (((size_t)zb * NMB + mb) * NKS) * 32 + lane;

    float acc[NJ][4];
#pragma unroll
    for (int j = 0; j < NJ; j++)
#pragma unroll
        for (int q = 0; q < 4; q++) acc[j][q] = 0.0f;

    uint4 ahr[2], alr[2];

    auto ISSUE_B = [&](int ks) {
        const int slot = ks & (STAGES-1);
        cp_async16(&sB[slot][t],       Bb + ((size_t)(t >> 5)*NKS + ks)*32 + (t & 31));
        {
            int idx = t + 128;
            cp_async16(&sB[slot][idx], Bb + ((size_t)(idx >> 5)*NKS + ks)*32 + (idx & 31));
        }
        if (t < 32) {
            int idx = t + 256;
            cp_async16(&sB[slot][idx], Bb + ((size_t)(idx >> 5)*NKS + ks)*32 + (idx & 31));
        }
    };
    auto LD_A = [&](int ks, int p) {
        const size_t fidx = fbase + (size_t)ks * 32;
        ahr[p] = pAh[fidx];
        alr[p] = pAl[fidx];
    };

    ISSUE_B(0); cp_commit();
    ISSUE_B(1); cp_commit();
    LD_A(0, 0);

    for (int ks = 0; ks < NKS; ks++) {
        const int p = ks & 1;
        if (ks + 2 < NKS) ISSUE_B(ks + 2);
        cp_commit();
        if (ks + 1 < NKS) LD_A(ks + 1, p ^ 1);

        cp_wait<2>();
        __syncthreads();

        uint32_t ah[4], al[4];
        ah[0] = ahr[p].x; ah[1] = ahr[p].y; ah[2] = ahr[p].z; ah[3] = ahr[p].w;
        al[0] = alr[p].x; al[1] = alr[p].y; al[2] = alr[p].z; al[3] = alr[p].w;

        const uint4* bs = &sB[ks & (STAGES-1)][lane];
#pragma unroll
        for (int j = 0; j < NJ; j++) {
            uint4 bj = bs[j*32];
            uint32_t bh[2], bl[2];
            bh[0] = bj.x; bh[1] = bj.y;
            bl[0] = bj.z; bl[1] = bj.w;
            mma_bf16(acc[j], ah, bh);
            mma_bf16(acc[j], al, bh);
            mma_bf16(acc[j], ah, bl);
        }
    }

#pragma unroll
    for (int j = 0; j < NJ; j++) {
        int col = j*8 + 2*tg;
        if (col < DCAT) {
#pragma unroll
            for (int h2 = 0; h2 < 2; h2++) {
                int row = row0 + g + h2*8;
                size_t o = ((size_t)b * NN + row) * DCAT + col;
                float2 v;
                v.x = alpha * acc[j][h2*2 + 0];
                v.y = alpha * acc[j][h2*2 + 1];
                if (Base) {
                    float2 bs2 = *(const float2*)(Base + o);
                    v.x = fmaf(beta, bs2.x, v.x);
                    v.y = fmaf(beta, bs2.y, v.y);
                }
                *(float2*)(Out + o) = v;
            }
        }
    }
}

// ---------------------------------------------------------------------------
// Kernel 3: gate combine — fused pack of candidate
// ---------------------------------------------------------------------------
__global__ __launch_bounds__(384) void combine_gate(
                             const float* __restrict__ X,
                             const float* __restrict__ T0,
                             const float* __restrict__ T1,
                             const float* __restrict__ T2,
                             const float* __restrict__ T3,
                             const float* __restrict__ gate_w,
                             const float* __restrict__ gate_b,
                             const float* __restrict__ xt,
                             const float* __restrict__ s1,
                             const float* __restrict__ s2,
                             float* __restrict__ cand,
                             float* __restrict__ r_out,
                             uint4* __restrict__ packC)
{
    __shared__ float s[16][DBASIS];
    __shared__ float cnd[16][68];
    const int t  = threadIdx.x;
    const int nb = blockIdx.x * 16;

    for (int idx = t; idx < 16*DBASIS; idx += 384) {
        int n = idx / DBASIS, i = idx - n*DBASIS;
        int term = i / DCAT, w = i - term*DCAT;
        const float* src;
        switch (term) {
            case 0: src = X;  break;
            case 1: src = T0; break;
            case 2: src = T1; break;
            case 3: src = X;  break;
            case 4: src = T2; break;
            default: src = T3; break;
        }
        s[n][i] = src[(size_t)(nb+n)*DCAT + w];
    }
    __syncthreads();

    const int c = t % 96;
    const int g = t / 96;
    float acc[4];
    float bc = gate_b[c];
#pragma unroll
    for (int q = 0; q < 4; q++) acc[q] = bc;

    for (int i = 0; i < DBASIS; i++) {
        float w = __ldg(&gate_w[i*GOUT + c]);
#pragma unroll
        for (int q = 0; q < 4; q++)
            acc[q] = fmaf(s[g*4 + q][i], w, acc[q]);
    }

#pragma unroll
    for (int q = 0; q < 4; q++) {
        int n = g*4 + q;
        int node = nb + n;
        float v = sigmoidf_(acc[q]);
        if (c < DO) {
            float cv = v * s1[node*DS + c];
            cand[(size_t)node*DCAT + DIN + c] = cv;
            cnd[n][DIN + c] = cv;
        } else if (c < 2*DO) {
            int cc = c - DO;
            float cv = v * s2[node*DS + cc];
            cand[(size_t)node*DCAT + DIN + DS + cc] = cv;
            cnd[n][DIN + DS + cc] = cv;
        } else {
            r_out[node*DO + (c - 2*DO)] = v;
        }
        if (c < DIN) {
            float cv = xt[node*DIN + c];
            cand[(size_t)node*DCAT + c] = cv;
            cnd[n][c] = cv;
        }
    }
    __syncthreads();

    if (t < 288) {
        const int bb = nb >> 11;
        const int kb = (nb & 2047) >> 4;
        pack_tile<68>(cnd, packC, bb, kb, t);
    }
}

// ---------------------------------------------------------------------------
// Kernel 4: final
// ---------------------------------------------------------------------------
__global__ __launch_bounds__(512) void final_kernel(
                             const float* __restrict__ C,
                             const float* __restrict__ T0,
                             const float* __restrict__ T1,
                             const float* __restrict__ T2,
                             const float* __restrict__ T3,
                             const float* __restrict__ upd_w,
                             const float* __restrict__ upd_b,
                             const float* __restrict__ hop_w,
                             const float* __restrict__ hop_b,
                             const float* __restrict__ g_r,
                             const float* __restrict__ g_state,
                             float* __restrict__ out)
{
    __shared__ float s[16][DBASIS];
    __shared__ float hsh[16][DO];
    const int t  = threadIdx.x;
    const int nb = blockIdx.x * 16;

    for (int idx = t; idx < 16*DBASIS; idx += 512) {
        int n = idx / DBASIS, i = idx - n*DBASIS;
        int term = i / DCAT, w = i - term*DCAT;
        const float* src;
        switch (term) {
            case 0: src = C;  break;
            case 1: src = T0; break;
            case 2: src = T1; break;
            case 3: src = C;  break;
            case 4: src = T2; break;
            default: src = T3; break;
        }
        s[n][i] = src[(size_t)(nb+n)*DCAT + w];
    }
    __syncthreads();

    const int n = t >> 5;
    const int c = t & 31;
    const int node = nb + n;

    float acc = upd_b[c];
    for (int i = 0; i < DBASIS; i++)
        acc = fmaf(s[n][i], __ldg(&upd_w[i*DO + c]), acc);

    float hc = tanhf(acc);
    float r  = g_r[node*DO + c];
    float st = g_state[node*DS + c];
    float h  = r*st + (1.0f - r)*hc;

    out[(size_t)node*DO + c] = h;
    hsh[n][c] = h;
    __syncthreads();

    float a2 = hop_b[c];
#pragma unroll
    for (int i = 0; i < HID; i++)
        a2 = fmaf(hsh[n][i], hop_w[i*HID + c], a2);
    out[(size_t)TOTN*DO + (size_t)node*HID + c] = a2;
}

// ---------------------------------------------------------------------------
// launch
// ---------------------------------------------------------------------------
extern "C" void kernel_launch(void* const* d_in, const int* in_sizes, int n_in,
                              void* d_out, int out_size)
{
    const float* xt     = (const float*)d_in[0];
    const float* s1     = (const float*)d_in[1];
    const float* s2     = (const float*)d_in[2];
    const float* ge     = (const float*)d_in[3];
    const float* sup    = (const float*)d_in[4];
    const float* mlp_w  = (const float*)d_in[5];
    const float* mlp_b  = (const float*)d_in[6];
    const float* gate_w = (const float*)d_in[7];
    const float* gate_b = (const float*)d_in[8];
    const float* upd_w  = (const float*)d_in[9];
    const float* upd_b  = (const float*)d_in[10];
    const float* hop_w  = (const float*)d_in[11];
    const float* hop_b  = (const float*)d_in[12];
    float* out = (float*)d_out;

    float* scr = nullptr;
    cudaGetSymbolAddress((void**)&scr, g_scratch);
    uint4* pA = nullptr;
    cudaGetSymbolAddress((void**)&pA, g_packA);
    uint4* pB = nullptr;
    cudaGetSymbolAddress((void**)&pB, g_packB);
    uint4* pAh = nullptr;
    cudaGetSymbolAddress((void**)&pAh, g_packAh);
    uint4* pAl = nullptr;
    cudaGetSymbolAddress((void**)&pAl, g_packAl);

    float* gX  = scr + OFF_X;
    float* gC  = scr + OFF_C;
    float* gT0 = scr + OFF_T0;
    float* gT1 = scr + OFF_T1;
    float* gT2 = scr + OFF_T2;
    float* gT3 = scr + OFF_T3;
    float* gST = scr + OFF_ST;
    float* gR  = scr + OFF_R;

    dim3 ggrid(NN / 64, BB, 2);     // z = support
    dim3 pgrid(NKS, BB, 2);         // z = T0 / T2

    prep_kernel<<<TOTN/16, 512>>>(xt, s1, s2, ge, mlp_w, mlp_b, gX, gST, pA);

    // launch 1: T0/T2 = A·X  — also persists packed A fragments
    gemm_first<<<ggrid, 128>>>(sup, pA, gT0, pAh, pAl);
    pack_kernel<<<pgrid, 288>>>(gT0, 2*SZ66, pB);
    // launch 2: T1/T3 = 2A·T0 − X  (packed A; pB has 2 slots -> stride PACK_ELEMS)
    gemm_packed<<<ggrid, 128>>>(pAh, pAl, pB, PACK_ELEMS, gX, gT1, 2.0f, -1.0f);

    combine_gate<<<TOTN/16, 384>>>(gX, gT0, gT1, gT2, gT3,
                                   gate_w, gate_b, xt, s1, s2, gC, gR, pA);

    // launch 3: T0'/T2' = A·C  (packed A; pA is a SINGLE shared image -> stride 0)
    gemm_packed<<<ggrid, 128>>>(pAh, pAl, pA, 0, nullptr, gT0, 1.0f, 0.0f);
    pack_kernel<<<pgrid, 288>>>(gT0, 2*SZ66, pB);
    // launch 4: T1'/T3' = 2A·T0' − C  (packed A; pB stride PACK_ELEMS)
    gemm_packed<<<ggrid, 128>>>(pAh, pAl, pB, PACK_ELEMS, gC, gT1, 2.0f, -1.0f);

    final_kernel<<<TOTN/16, 512>>>(gC, gT0, gT1, gT2, gT3,
                                   upd_w, upd_b, hop_w, hop_b,
                                   gR, gST, out);
}

// round 17
// speedup vs baseline: 1.2579x; 1.2579x over previous
#include <cuda_runtime.h>
#include <cuda_bf16.h>
#include <cstdint>

// ---------------- problem constants ----------------
#define BB   8
#define NN   2048
#define DIN  2
#define DS   32
#define DO   32
#define GE   8
#define HID  32
#define DCAT 66
#define DGI  74
#define DBASIS 396
#define GOUT 96

#define TOTN (BB*NN)
#define SZ66 ((size_t)TOTN*DCAT)
#define SZ32 ((size_t)TOTN*DO)

#define NJ 9                 // n8 blocks (72 cols, 66 used)
#define NKS 128              // k16 blocks
#define PACK_ELEMS ((size_t)BB*NJ*NKS*32)        // uint4 per B pack image

__device__ float g_scratch[6*1081344 + 2*524288];
__device__ uint4 g_packA[PACK_ELEMS];       // packed X or C (shared by both supports)
__device__ uint4 g_packB[2*PACK_ELEMS];     // packed T0 (slot0) / T2 (slot1)

#define OFF_X  ((size_t)0)
#define OFF_C  (SZ66)
#define OFF_T0 (2*SZ66)
#define OFF_T1 (3*SZ66)
#define OFF_T2 (4*SZ66)
#define OFF_T3 (5*SZ66)
#define OFF_ST (6*SZ66)
#define OFF_R  (6*SZ66 + SZ32)

__device__ __forceinline__ float sigmoidf_(float x) {
    return 1.0f / (1.0f + __expf(-x));
}

__device__ __forceinline__ void mma_bf16(float c[4], const uint32_t a[4], const uint32_t b[2]) {
    asm volatile(
        "mma.sync.aligned.m16n8k16.row.col.f32.bf16.bf16.f32 "
        "{%0,%1,%2,%3},{%4,%5,%6,%7},{%8,%9},{%0,%1,%2,%3};"
        : "+f"(c[0]), "+f"(c[1]), "+f"(c[2]), "+f"(c[3])
        : "r"(a[0]), "r"(a[1]), "r"(a[2]), "r"(a[3]), "r"(b[0]), "r"(b[1]));
}

__device__ __forceinline__ void cp_async16(void* smem, const void* gmem) {
    uint32_t s = (uint32_t)__cvta_generic_to_shared(smem);
    asm volatile("cp.async.cg.shared.global [%0], [%1], 16;\n" :: "r"(s), "l"(gmem));
}
__device__ __forceinline__ void cp_commit() {
    asm volatile("cp.async.commit_group;\n" ::: "memory");
}
template<int N>
__device__ __forceinline__ void cp_wait() {
    asm volatile("cp.async.wait_group %0;\n" :: "n"(N) : "memory");
}

// split float2 -> bf16x2 high + bf16x2 low-residual
__device__ __forceinline__ void split2(float2 v, uint32_t& h, uint32_t& l) {
    __nv_bfloat162 hh = __float22bfloat162_rn(v);
    h = *(uint32_t*)&hh;
    float2 r;
    r.x = v.x - __low2float(hh);
    r.y = v.y - __high2float(hh);
    __nv_bfloat162 ll = __float22bfloat162_rn(r);
    l = *(uint32_t*)&ll;
}

// pack one 16-node x 66-col tile (smem) -> B fragment-native h/l image.
template<int TS>
__device__ __forceinline__ void pack_tile(const float (*tile)[TS], uint4* dst,
                                          int b, int kb, int t)
{
    const int j    = t >> 5;
    const int lane = t & 31;
    const int g    = lane >> 2;
    const int tg   = lane & 3;
    const int n    = j*8 + g;

    float v0 = 0.f, v1 = 0.f, v2 = 0.f, v3 = 0.f;
    if (n < DCAT) {
        v0 = tile[2*tg    ][n];
        v1 = tile[2*tg + 1][n];
        v2 = tile[2*tg + 8][n];
        v3 = tile[2*tg + 9][n];
    }
    uint32_t h01, l01, h89, l89;
    split2(make_float2(v0, v1), h01, l01);
    split2(make_float2(v2, v3), h89, l89);

    uint4 o; o.x = h01; o.y = h89; o.z = l01; o.w = l89;
    dst[((size_t)(b*NJ + j)*NKS + kb)*32 + lane] = o;
}

// ---------------------------------------------------------------------------
// Kernel 1: prep — gate MLP -> mr -> state; write X and packed X
// ---------------------------------------------------------------------------
__global__ __launch_bounds__(512) void prep_kernel(
                            const float* __restrict__ xt,
                            const float* __restrict__ s1,
                            const float* __restrict__ s2,
                            const float* __restrict__ ge,
                            const float* __restrict__ mlp_w,
                            const float* __restrict__ mlp_b,
                            float* __restrict__ gX,
                            float* __restrict__ gstate,
                            uint4* __restrict__ packX)
{
    __shared__ float sg[16][DGI];
    const int t  = threadIdx.x;
    const int nb = blockIdx.x * 16;

    for (int idx = t; idx < 16 * DGI; idx += 512) {
        int nn = idx / DGI, i = idx % DGI;
        int node = nb + nn;
        float v;
        if (i < DIN)            v = xt[node*DIN + i];
        else if (i < DIN+DS)    v = s1[node*DS + (i-DIN)];
        else if (i < DIN+2*DS)  v = s2[node*DS + (i-DIN-DS)];
        else                    v = ge[node*GE + (i-DIN-2*DS)];
        sg[nn][i] = v;
    }
    __syncthreads();

    for (int idx = t; idx < 16 * DCAT; idx += 512) {
        int nn = idx / DCAT, i = idx % DCAT;
        gX[(size_t)(nb+nn)*DCAT + i] = sg[nn][i];
    }

    const int n = t >> 5;
    const int c = t & 31;
    float acc = mlp_b[c];
#pragma unroll 8
    for (int i = 0; i < DGI; i++)
        acc = fmaf(sg[n][i], mlp_w[i*DO + c], acc);
    float mr = sigmoidf_(acc);

    int node = nb + n;
    float a = s1[node*DS + c];
    float b = s2[node*DS + c];
    gstate[node*DS + c] = mr*a + (1.0f - mr)*b;

    if (t < 288) {
        const int bb = nb >> 11;
        const int kb = (nb & 2047) >> 4;
        pack_tile<DGI>(sg, packX, bb, kb, t);
    }
}

// ---------------------------------------------------------------------------
// Pack kernel (T0/T2): grid (128, 8, 2)
// ---------------------------------------------------------------------------
__global__ __launch_bounds__(288) void pack_kernel(const float* __restrict__ src,
                                                   size_t srcStride,
                                                   uint4* __restrict__ dst)
{
    __shared__ float tile[16][68];
    const int t  = threadIdx.x;
    const int kb = blockIdx.x;
    const int b  = blockIdx.y;
    const int z  = blockIdx.z;
    src += (size_t)z * srcStride;
    dst += (size_t)z * PACK_ELEMS;
    const int node0 = b*NN + kb*16;

    for (int idx = t; idx < 16*DCAT; idx += 288) {
        int r = idx / DCAT, c = idx - r*DCAT;
        tile[r][c] = src[(size_t)(node0 + r)*DCAT + c];
    }
    __syncthreads();
    pack_tile<68>(tile, dst, b, kb, t);
}

// ---------------------------------------------------------------------------
// Kernel 2: GEMM — BOTH operands streamed via cp.async 4-stage ring.
//   A: fp32 64x16 CTA tile (4KB/stage, coalesced), fragment gather via LDS.64,
//      in-reg bf16 h/l split (3-product).
//   B: packed fragment image (4.6KB/stage), LDS.128.
// CTA 128 thr = 4 warps x m16 (M-tile 64); grid (32, 8, 2); z = support.
// bpStride: 0 when B image shared by supports (X/C), PACK_ELEMS for T0/T2.
// ---------------------------------------------------------------------------
#define STAGES 4

__global__ __launch_bounds__(128) void gemm_cheb(const float* __restrict__ A,
                                                 const uint4* __restrict__ Bp,
                                                 size_t bpStride,
                                                 const float* __restrict__ Base,
                                                 float* __restrict__ Out,
                                                 float alpha, float beta)
{
    __shared__ float sA[STAGES][64][16];    // 16 KB
    __shared__ uint4 sB[STAGES][NJ*32];     // 18.4 KB

    const int z = blockIdx.z;
    A   += (size_t)z * BB * NN * NN;
    Bp  += (size_t)z * bpStride;
    Out += (size_t)z * 2 * SZ66;

    const int t    = threadIdx.x;
    const int w    = t >> 5;
    const int lane = t & 31;
    const int g    = lane >> 2;
    const int tg   = lane & 3;
    const int b    = blockIdx.y;
    const int row0 = blockIdx.x * 64;

    const float* Ab = A + ((size_t)b * NN + row0) * NN;
    const uint4* Bb = Bp + (size_t)b * NJ * NKS * 32;

    float acc[NJ][4];
#pragma unroll
    for (int j = 0; j < NJ; j++)
#pragma unroll
        for (int q = 0; q < 4; q++) acc[j][q] = 0.0f;

    auto ISSUE = [&](int ks) {
        const int slot = ks & (STAGES-1);
        // A tile: 256 x 16B granules (row = gi/4, 4 floats each)
#pragma unroll
        for (int rep = 0; rep < 2; rep++) {
            int gi  = t + rep*128;
            int row = gi >> 2;
            int ko  = (gi & 3) * 4;
            cp_async16(&sA[slot][row][ko], Ab + (size_t)row*NN + ks*16 + ko);
        }
        // B image: 288 x 16B granules
        cp_async16(&sB[slot][t],       Bb + ((size_t)(t >> 5)*NKS + ks)*32 + (t & 31));
        {
            int idx = t + 128;
            cp_async16(&sB[slot][idx], Bb + ((size_t)(idx >> 5)*NKS + ks)*32 + (idx & 31));
        }
        if (t < 32) {
            int idx = t + 256;
            cp_async16(&sB[slot][idx], Bb + ((size_t)(idx >> 5)*NKS + ks)*32 + (idx & 31));
        }
    };

    ISSUE(0); cp_commit();
    ISSUE(1); cp_commit();

    for (int ks = 0; ks < NKS; ks++) {
        if (ks + 2 < NKS) ISSUE(ks + 2);
        cp_commit();                       // uniform group count
        cp_wait<2>();                      // stage ks landed
        __syncthreads();

        const int slot = ks & (STAGES-1);

        // A fragment gather + in-reg split (same fragment order as before)
        float2 a0 = *(const float2*)&sA[slot][w*16 + g    ][2*tg];
        float2 a1 = *(const float2*)&sA[slot][w*16 + g + 8][2*tg];
        float2 a2 = *(const float2*)&sA[slot][w*16 + g    ][2*tg + 8];
        float2 a3 = *(const float2*)&sA[slot][w*16 + g + 8][2*tg + 8];

        uint32_t ah[4], al[4];
        split2(a0, ah[0], al[0]);
        split2(a1, ah[1], al[1]);
        split2(a2, ah[2], al[2]);
        split2(a3, ah[3], al[3]);

        const uint4* bs = &sB[slot][lane];
#pragma unroll
        for (int j = 0; j < NJ; j++) {
            uint4 bj = bs[j*32];
            uint32_t bh[2], bl[2];
            bh[0] = bj.x; bh[1] = bj.y;
            bl[0] = bj.z; bl[1] = bj.w;
            mma_bf16(acc[j], ah, bh);
            mma_bf16(acc[j], al, bh);
            mma_bf16(acc[j], ah, bl);
        }
    }

    // epilogue
#pragma unroll
    for (int j = 0; j < NJ; j++) {
        int col = j*8 + 2*tg;
        if (col < DCAT) {
#pragma unroll
            for (int h2 = 0; h2 < 2; h2++) {
                int row = row0 + w*16 + g + h2*8;
                size_t o = ((size_t)b * NN + row) * DCAT + col;
                float2 v;
                v.x = alpha * acc[j][h2*2 + 0];
                v.y = alpha * acc[j][h2*2 + 1];
                if (Base) {
                    float2 bs2 = *(const float2*)(Base + o);
                    v.x = fmaf(beta, bs2.x, v.x);
                    v.y = fmaf(beta, bs2.y, v.y);
                }
                *(float2*)(Out + o) = v;
            }
        }
    }
}

// ---------------------------------------------------------------------------
// Kernel 3: gate combine — fused pack of candidate
// ---------------------------------------------------------------------------
__global__ __launch_bounds__(384) void combine_gate(
                             const float* __restrict__ X,
                             const float* __restrict__ T0,
                             const float* __restrict__ T1,
                             const float* __restrict__ T2,
                             const float* __restrict__ T3,
                             const float* __restrict__ gate_w,
                             const float* __restrict__ gate_b,
                             const float* __restrict__ xt,
                             const float* __restrict__ s1,
                             const float* __restrict__ s2,
                             float* __restrict__ cand,
                             float* __restrict__ r_out,
                             uint4* __restrict__ packC)
{
    __shared__ float s[16][DBASIS];
    __shared__ float cnd[16][68];
    const int t  = threadIdx.x;
    const int nb = blockIdx.x * 16;

    for (int idx = t; idx < 16*DBASIS; idx += 384) {
        int n = idx / DBASIS, i = idx - n*DBASIS;
        int term = i / DCAT, w = i - term*DCAT;
        const float* src;
        switch (term) {
            case 0: src = X;  break;
            case 1: src = T0; break;
            case 2: src = T1; break;
            case 3: src = X;  break;
            case 4: src = T2; break;
            default: src = T3; break;
        }
        s[n][i] = src[(size_t)(nb+n)*DCAT + w];
    }
    __syncthreads();

    const int c = t % 96;
    const int g = t / 96;
    float acc[4];
    float bc = gate_b[c];
#pragma unroll
    for (int q = 0; q < 4; q++) acc[q] = bc;

    for (int i = 0; i < DBASIS; i++) {
        float w = __ldg(&gate_w[i*GOUT + c]);
#pragma unroll
        for (int q = 0; q < 4; q++)
            acc[q] = fmaf(s[g*4 + q][i], w, acc[q]);
    }

#pragma unroll
    for (int q = 0; q < 4; q++) {
        int n = g*4 + q;
        int node = nb + n;
        float v = sigmoidf_(acc[q]);
        if (c < DO) {
            float cv = v * s1[node*DS + c];
            cand[(size_t)node*DCAT + DIN + c] = cv;
            cnd[n][DIN + c] = cv;
        } else if (c < 2*DO) {
            int cc = c - DO;
            float cv = v * s2[node*DS + cc];
            cand[(size_t)node*DCAT + DIN + DS + cc] = cv;
            cnd[n][DIN + DS + cc] = cv;
        } else {
            r_out[node*DO + (c - 2*DO)] = v;
        }
        if (c < DIN) {
            float cv = xt[node*DIN + c];
            cand[(size_t)node*DCAT + c] = cv;
            cnd[n][c] = cv;
        }
    }
    __syncthreads();

    if (t < 288) {
        const int bb = nb >> 11;
        const int kb = (nb & 2047) >> 4;
        pack_tile<68>(cnd, packC, bb, kb, t);
    }
}

// ---------------------------------------------------------------------------
// Kernel 4: final
// ---------------------------------------------------------------------------
__global__ __launch_bounds__(512) void final_kernel(
                             const float* __restrict__ C,
                             const float* __restrict__ T0,
                             const float* __restrict__ T1,
                             const float* __restrict__ T2,
                             const float* __restrict__ T3,
                             const float* __restrict__ upd_w,
                             const float* __restrict__ upd_b,
                             const float* __restrict__ hop_w,
                             const float* __restrict__ hop_b,
                             const float* __restrict__ g_r,
                             const float* __restrict__ g_state,
                             float* __restrict__ out)
{
    __shared__ float s[16][DBASIS];
    __shared__ float hsh[16][DO];
    const int t  = threadIdx.x;
    const int nb = blockIdx.x * 16;

    for (int idx = t; idx < 16*DBASIS; idx += 512) {
        int n = idx / DBASIS, i = idx - n*DBASIS;
        int term = i / DCAT, w = i - term*DCAT;
        const float* src;
        switch (term) {
            case 0: src = C;  break;
            case 1: src = T0; break;
            case 2: src = T1; break;
            case 3: src = C;  break;
            case 4: src = T2; break;
            default: src = T3; break;
        }
        s[n][i] = src[(size_t)(nb+n)*DCAT + w];
    }
    __syncthreads();

    const int n = t >> 5;
    const int c = t & 31;
    const int node = nb + n;

    float acc = upd_b[c];
    for (int i = 0; i < DBASIS; i++)
        acc = fmaf(s[n][i], __ldg(&upd_w[i*DO + c]), acc);

    float hc = tanhf(acc);
    float r  = g_r[node*DO + c];
    float st = g_state[node*DS + c];
    float h  = r*st + (1.0f - r)*hc;

    out[(size_t)node*DO + c] = h;
    hsh[n][c] = h;
    __syncthreads();

    float a2 = hop_b[c];
#pragma unroll
    for (int i = 0; i < HID; i++)
        a2 = fmaf(hsh[n][i], hop_w[i*HID + c], a2);
    out[(size_t)TOTN*DO + (size_t)node*HID + c] = a2;
}

// ---------------------------------------------------------------------------
// launch
// ---------------------------------------------------------------------------
extern "C" void kernel_launch(void* const* d_in, const int* in_sizes, int n_in,
                              void* d_out, int out_size)
{
    const float* xt     = (const float*)d_in[0];
    const float* s1     = (const float*)d_in[1];
    const float* s2     = (const float*)d_in[2];
    const float* ge     = (const float*)d_in[3];
    const float* sup    = (const float*)d_in[4];
    const float* mlp_w  = (const float*)d_in[5];
    const float* mlp_b  = (const float*)d_in[6];
    const float* gate_w = (const float*)d_in[7];
    const float* gate_b = (const float*)d_in[8];
    const float* upd_w  = (const float*)d_in[9];
    const float* upd_b  = (const float*)d_in[10];
    const float* hop_w  = (const float*)d_in[11];
    const float* hop_b  = (const float*)d_in[12];
    float* out = (float*)d_out;

    float* scr = nullptr;
    cudaGetSymbolAddress((void**)&scr, g_scratch);
    uint4* pA = nullptr;
    cudaGetSymbolAddress((void**)&pA, g_packA);
    uint4* pB = nullptr;
    cudaGetSymbolAddress((void**)&pB, g_packB);

    float* gX  = scr + OFF_X;
    float* gC  = scr + OFF_C;
    float* gT0 = scr + OFF_T0;
    float* gT1 = scr + OFF_T1;
    float* gT2 = scr + OFF_T2;
    float* gT3 = scr + OFF_T3;
    float* gST = scr + OFF_ST;
    float* gR  = scr + OFF_R;

    dim3 ggrid(NN / 64, BB, 2);     // z = support
    dim3 pgrid(NKS, BB, 2);         // z = T0 / T2

    prep_kernel<<<TOTN/16, 512>>>(xt, s1, s2, ge, mlp_w, mlp_b, gX, gST, pA);

    // T0/T2 = A·X   (B image shared by supports -> stride 0)
    gemm_cheb<<<ggrid, 128>>>(sup, pA, 0, nullptr, gT0, 1.0f, 0.0f);
    pack_kernel<<<pgrid, 288>>>(gT0, 2*SZ66, pB);
    // T1/T3 = 2A·T0 − X   (pB has per-support slots -> stride PACK_ELEMS)
    gemm_cheb<<<ggrid, 128>>>(sup, pB, PACK_ELEMS, gX, gT1, 2.0f, -1.0f);

    combine_gate<<<TOTN/16, 384>>>(gX, gT0, gT1, gT2, gT3,
                                   gate_w, gate_b, xt, s1, s2, gC, gR, pA);

    // T0'/T2' = A·C   (shared image -> stride 0)
    gemm_cheb<<<ggrid, 128>>>(sup, pA, 0, nullptr, gT0, 1.0f, 0.0f);
    pack_kernel<<<pgrid, 288>>>(gT0, 2*SZ66, pB);
    // T1'/T3' = 2A·T0' − C
    gemm_cheb<<<ggrid, 128>>>(sup, pB, PACK_ELEMS, gC, gT1, 2.0f, -1.0f);

    final_kernel<<<TOTN/16, 512>>>(gC, gT0, gT1, gT2, gT3,
                                   upd_w, upd_b, hop_w, hop_b,
                                   gR, gST, out);
}